// round 4
// baseline (speedup 1.0000x reference)
#include <cuda_runtime.h>
#include <cuda_fp16.h>
#include <stdint.h>

#define THREADS 512

// Pre-transposed fp16 weights: Wt[n][k] (row-major over n, contiguous k)
__device__ __half g_Wt1[384 * 384];
__device__ __half g_Wt2[192 * 384];
__device__ __half g_Wt3[192 * 192];

__global__ void prep_weights(const float* __restrict__ W1,
                             const float* __restrict__ W2,
                             const float* __restrict__ W3) {
    int idx = blockIdx.x * blockDim.x + threadIdx.x;
    const int N1 = 384 * 384, N2 = 192 * 384, N3 = 192 * 192;
    if (idx < N1) {
        int n = idx / 384, k = idx % 384;
        g_Wt1[idx] = __float2half(W1[k * 384 + n]);
    } else if (idx < N1 + N2) {
        int i = idx - N1;
        int n = i / 384, k = i % 384;
        g_Wt2[i] = __float2half(W2[k * 192 + n]);
    } else if (idx < N1 + N2 + N3) {
        int i = idx - N1 - N2;
        int n = i / 192, k = i % 192;
        g_Wt3[i] = __float2half(W3[k * 192 + n]);
    }
}

// Smem layout (bytes):
//   sSrc : half[128*200]  @ 0        (51200)  x_src embeds, stride 200 halves
//   sDst : half[8*200]    @ 51200    (3200)   x_dst embeds (8 unique per tile)
//   sH1  : half[128*392]  @ 54400    (100352) h1 (layer1 out), stride 392
//   sW   : half[192*72]   @ 154752   (27648)  weight K-chunk stage, stride 72
//   sH3  : float[128*196] overlays sH1 region (layer3 fp32 out, stride 196)
// Total 182400 B. All strides are ≡ 4 (mod 32) in 32-bit words -> conflict-free
// mma fragment loads (8 rows x 4 col-pairs hit 32 distinct banks).
#define SMEM_TOTAL 182400

// One 128x192 output pass: C[128x192] (+bias) = A[128xK] @ Wt[nBase..nBase+192)^T
// 16 warps as 4x4 grid of 32x48 warp tiles; m16n8k16 fp16 MMA, fp32 accum.
__device__ __forceinline__ void mma_pass(
    int tid, int rowBase, int colBase, int grp, int tig,
    const __half* __restrict__ gW, int ldW, int nBase, int K,
    const __half* A0, const __half* A1, int strideA, int kSplit,
    __half* sW,
    bool doGelu, __half* outH, int strideOutH, int outColBase,
    float* outF, int strideOutF,
    const float* __restrict__ bias)
{
    float C[2][6][4];
#pragma unroll
    for (int mf = 0; mf < 2; mf++)
#pragma unroll
        for (int nf = 0; nf < 6; nf++)
#pragma unroll
            for (int q = 0; q < 4; q++) C[mf][nf][q] = 0.f;

    for (int kc = 0; kc < K; kc += 64) {
        __syncthreads();
        // Stage Wt[nBase+0..191][kc..kc+63] -> sW (192 rows x 64 halves, stride 72)
#pragma unroll
        for (int it = 0; it < 3; it++) {
            int i = tid + it * THREADS;           // 0..1535
            int rw = i >> 3, v = i & 7;
            *(uint4*)(sW + rw * 72 + v * 8) =
                *(const uint4*)(gW + (nBase + rw) * ldW + kc + v * 8);
        }
        __syncthreads();
#pragma unroll
        for (int ks = 0; ks < 4; ks++) {
            int kb = kc + ks * 16;
            // A source select (layer1: k<192 -> src rows, k>=192 -> dst rows r>>4)
            const __half* Ab; int sh, ac;
            if (kb < kSplit) { Ab = A0; sh = 0; ac = kb; }
            else             { Ab = A1; sh = 4; ac = kb - kSplit; }
            uint32_t a[2][4];
#pragma unroll
            for (int mf = 0; mf < 2; mf++) {
                int r0 = rowBase + mf * 16 + grp;
                int r1 = r0 + 8;
                int c0 = ac + tig * 2;
                a[mf][0] = *(const uint32_t*)(Ab + (r0 >> sh) * strideA + c0);
                a[mf][1] = *(const uint32_t*)(Ab + (r1 >> sh) * strideA + c0);
                a[mf][2] = *(const uint32_t*)(Ab + (r0 >> sh) * strideA + c0 + 8);
                a[mf][3] = *(const uint32_t*)(Ab + (r1 >> sh) * strideA + c0 + 8);
            }
#pragma unroll
            for (int nf = 0; nf < 6; nf++) {
                int n  = colBase + nf * 8 + grp;
                int kk = ks * 16 + tig * 2;
                uint32_t b0 = *(const uint32_t*)(sW + n * 72 + kk);
                uint32_t b1 = *(const uint32_t*)(sW + n * 72 + kk + 8);
#pragma unroll
                for (int mf = 0; mf < 2; mf++) {
                    asm volatile(
                        "mma.sync.aligned.m16n8k16.row.col.f32.f16.f16.f32 "
                        "{%0,%1,%2,%3}, {%4,%5,%6,%7}, {%8,%9}, {%0,%1,%2,%3};\n"
                        : "+f"(C[mf][nf][0]), "+f"(C[mf][nf][1]),
                          "+f"(C[mf][nf][2]), "+f"(C[mf][nf][3])
                        : "r"(a[mf][0]), "r"(a[mf][1]),
                          "r"(a[mf][2]), "r"(a[mf][3]),
                          "r"(b0), "r"(b1));
                }
            }
        }
    }
    // Epilogue: bias (+ exact gelu) -> half buffer or fp32 buffer.
    // No sync needed: output buffers never alias the A/W buffers of this pass;
    // the next pass's leading __syncthreads orders everything.
#pragma unroll
    for (int mf = 0; mf < 2; mf++) {
        int r0 = rowBase + mf * 16 + grp;
        int r1 = r0 + 8;
#pragma unroll
        for (int nf = 0; nf < 6; nf++) {
            int cl = colBase + nf * 8 + tig * 2;
            float bv0 = bias[cl];
            float bv1 = bias[cl + 1];
            float v00 = C[mf][nf][0] + bv0;
            float v01 = C[mf][nf][1] + bv1;
            float v10 = C[mf][nf][2] + bv0;
            float v11 = C[mf][nf][3] + bv1;
            if (doGelu) {                 // exact gelu: x * Phi(x)
                v00 *= normcdff(v00);
                v01 *= normcdff(v01);
                v10 *= normcdff(v10);
                v11 *= normcdff(v11);
            }
            if (outH) {
                *(__half2*)(outH + r0 * strideOutH + outColBase + cl) =
                    __floats2half2_rn(v00, v01);
                *(__half2*)(outH + r1 * strideOutH + outColBase + cl) =
                    __floats2half2_rn(v10, v11);
            } else {
                outF[r0 * strideOutF + cl]     = v00;
                outF[r0 * strideOutF + cl + 1] = v01;
                outF[r1 * strideOutF + cl]     = v10;
                outF[r1 * strideOutF + cl + 1] = v11;
            }
        }
    }
}

__global__ __launch_bounds__(THREADS, 1)
void fused_mlp_pool(const float* __restrict__ pos,
                    const int*   __restrict__ edges,
                    const float* __restrict__ b1,
                    const float* __restrict__ b2,
                    const float* __restrict__ b3,
                    float* __restrict__ out)
{
    extern __shared__ char smem[];
    __half* sSrc = (__half*)(smem);
    __half* sDst = (__half*)(smem + 51200);
    __half* sH1  = (__half*)(smem + 54400);
    __half* sW   = (__half*)(smem + 154752);
    float*  sH3  = (float*)(smem + 54400);

    const int tile = blockIdx.x;
    const int tid  = threadIdx.x;
    const int lane = tid & 31;
    const int wid  = tid >> 5;
    const int grp  = lane >> 2;
    const int tig  = lane & 3;
    const int rowBase = (wid >> 2) * 32;
    const int colBase = (wid & 3) * 48;

    // ---- sincos embedding into smem (fp16) ----
    // omega_j = 10000^(-j/32) = 2^(-j*log2(10000)/32)
    const float NLOG = -0.41524101186092033f;
    for (int i = tid; i < 128 * 96; i += THREADS) {
        int r = i / 96, q = i - r * 96;
        int d = q >> 5, j = q & 31;
        int src = edges[(tile * 128 + r) * 2 + 1];
        float c = pos[src * 3 + d];
        float w = exp2f((float)j * NLOG);
        float s, co;
        sincosf(c * w, &s, &co);
        sSrc[r * 200 + d * 64 + j]      = __float2half(s);
        sSrc[r * 200 + d * 64 + 32 + j] = __float2half(co);
    }
    for (int i = tid; i < 8 * 96; i += THREADS) {
        int g = i / 96, q = i - g * 96;
        int d = q >> 5, j = q & 31;
        int dv = edges[(tile * 128 + g * 16) * 2];
        float c = pos[dv * 3 + d];
        float w = exp2f((float)j * NLOG);
        float s, co;
        sincosf(c * w, &s, &co);
        sDst[g * 200 + d * 64 + j]      = __float2half(s);
        sDst[g * 200 + d * 64 + 32 + j] = __float2half(co);
    }
    // (first mma_pass begins with __syncthreads -> embeddings visible)

    // Layer 1 (K=384: k<192 from sSrc, k>=192 from sDst[r>>4]) -> gelu -> sH1
    mma_pass(tid, rowBase, colBase, grp, tig, g_Wt1, 384, 0, 384,
             sSrc, sDst, 200, 192, sW,
             true, sH1, 392, 0, nullptr, 0, b1);
    mma_pass(tid, rowBase, colBase, grp, tig, g_Wt1, 384, 192, 384,
             sSrc, sDst, 200, 192, sW,
             true, sH1, 392, 192, nullptr, 0, b1 + 192);
    // Layer 2: h1 @ W2 -> gelu -> h2 (reuses sSrc region)
    mma_pass(tid, rowBase, colBase, grp, tig, g_Wt2, 384, 0, 384,
             sH1, sH1, 392, 1 << 20, sW,
             true, sSrc, 200, 0, nullptr, 0, b2);
    // Layer 3: h2 @ W3 + b3 -> fp32 sH3 (overlays sH1 region)
    mma_pass(tid, rowBase, colBase, grp, tig, g_Wt3, 192, 0, 192,
             sSrc, sSrc, 200, 1 << 20, sW,
             false, nullptr, 0, 0, sH3, 196, b3);

    __syncthreads();
    // Segment mean: 8 groups of 16 consecutive rows, /16 (DEG exact)
    for (int i = tid; i < 8 * 192; i += THREADS) {
        int g = i / 192, c = i - g * 192;
        float s = 0.f;
#pragma unroll
        for (int r = 0; r < 16; r++) s += sH3[(g * 16 + r) * 196 + c];
        out[(tile * 8 + g) * 192 + c] = s * 0.0625f;
    }
}

extern "C" void kernel_launch(void* const* d_in, const int* in_sizes, int n_in,
                              void* d_out, int out_size) {
    const float* pos   = (const float*)d_in[0];
    const int*   edges = (const int*)d_in[1];
    // d_in[2] = batch_idx (unused by the reference computation)
    const float* W1 = (const float*)d_in[3];
    const float* b1 = (const float*)d_in[4];
    const float* W2 = (const float*)d_in[5];
    const float* b2 = (const float*)d_in[6];
    const float* W3 = (const float*)d_in[7];
    const float* b3 = (const float*)d_in[8];
    float* out = (float*)d_out;

    const int totalW = 384 * 384 + 192 * 384 + 192 * 192;
    prep_weights<<<(totalW + 255) / 256, 256>>>(W1, W2, W3);

    cudaFuncSetAttribute(fused_mlp_pool,
                         cudaFuncAttributeMaxDynamicSharedMemorySize, SMEM_TOTAL);
    fused_mlp_pool<<<2048, THREADS, SMEM_TOTAL>>>(pos, edges, b1, b2, b3, out);
}

// round 5
// speedup vs baseline: 1.2849x; 1.2849x over previous
#include <cuda_runtime.h>
#include <cuda_fp16.h>
#include <stdint.h>

#define THREADS 256

// Pre-transposed fp16 weights: Wt[n][k] (row-major over n, contiguous k)
__device__ __half g_Wt1[384 * 384];
__device__ __half g_Wt2[192 * 384];
__device__ __half g_Wt3[192 * 192];

__global__ void prep_weights(const float* __restrict__ W1,
                             const float* __restrict__ W2,
                             const float* __restrict__ W3) {
    int idx = blockIdx.x * blockDim.x + threadIdx.x;
    const int N1 = 384 * 384, N2 = 192 * 384, N3 = 192 * 192;
    if (idx < N1) {
        int n = idx / 384, k = idx % 384;
        g_Wt1[idx] = __float2half(W1[k * 384 + n]);
    } else if (idx < N1 + N2) {
        int i = idx - N1;
        int n = i / 384, k = i % 384;
        g_Wt2[i] = __float2half(W2[k * 192 + n]);
    } else if (idx < N1 + N2 + N3) {
        int i = idx - N1 - N2;
        int n = i / 192, k = i % 192;
        g_Wt3[i] = __float2half(W3[k * 192 + n]);
    }
}

// Smem layout (bytes), 64-edge tile:
//   sSrc : half[64*200]   @ 0       (25600)   src embeds, stride 200 halves
//   sDst : half[4*200]    @ 25600   (1600)    dst embeds (4 unique per tile)
//   sH1  : half[64*392]   @ 27200   (50176)   layer1 out, stride 392
//          (float[64*196] overlays this region for layer3 fp32 out)
//   sW   : half[2*192*40] @ 77376   (30720)   double-buffered weight chunks
// Total 108096 B -> 2 CTAs / SM.
// All strides (200, 392, 40 halves) are ≡ 4 mod 32 in 32-bit words ->
// conflict-free ldmatrix row accesses.
#define OFF_DST 25600
#define OFF_H1  27200
#define OFF_W   77376
#define SMEM_TOTAL 108096
#define W_STAGE 7680   // 192*40 halves per stage

__device__ __forceinline__ uint32_t smem_u32(const void* p) {
    return (uint32_t)__cvta_generic_to_shared(p);
}

__device__ __forceinline__ void ldsm_x4(uint32_t r[4], const __half* p) {
    uint32_t a = smem_u32(p);
    asm volatile("ldmatrix.sync.aligned.m8n8.x4.shared.b16 {%0,%1,%2,%3}, [%4];\n"
                 : "=r"(r[0]), "=r"(r[1]), "=r"(r[2]), "=r"(r[3]) : "r"(a));
}

__device__ __forceinline__ void cp16(__half* dst, const __half* src) {
    uint32_t s = smem_u32(dst);
    asm volatile("cp.async.cg.shared.global [%0], [%1], 16;\n" :: "r"(s), "l"(src));
}
#define CP_COMMIT() asm volatile("cp.async.commit_group;\n")
#define CP_WAIT0()  asm volatile("cp.async.wait_group 0;\n" ::: "memory")

// One 64x192 output pass: C (+bias, opt gelu) = A[64xK] @ Wt[nBase..+192)^T.
// 8 warps as 2x4 grid of 32x48 warp tiles; m16n8k16 fp16 MMA, fp32 accum.
// Weight K-chunks of 32 are cp.async double-buffered; one barrier per chunk.
__device__ __forceinline__ void mma_pass(
    int tid, int lane, int rowBase, int colBase,
    const __half* __restrict__ gW, int ldW, int nBase, int K,
    const __half* A0, const __half* A1, int strideA, int kSplit,
    __half* sW,
    bool doGelu, __half* outH, int strideOutH, int outColBase,
    float* outF, int strideOutF,
    const float* __restrict__ bias)
{
    // ldmatrix per-lane row/col offsets
    const int arow = (lane & 7) + ((lane >> 3) & 1) * 8;  // A: m within 16
    const int akof = (lane >> 4) * 8;                     // A: k offset
    const int brow = (lane & 7) + (lane >> 4) * 8;        // B: n within 16
    const int bkof = ((lane >> 3) & 1) * 8;               // B: k offset

    const int nCh = K >> 5;

    // prologue: stage chunk 0
#pragma unroll
    for (int it = 0; it < 3; it++) {
        int i = tid + it * THREADS;
        int rw = i >> 2, v = i & 3;
        cp16(sW + rw * 40 + v * 8, gW + (nBase + rw) * ldW + v * 8);
    }
    CP_COMMIT();

    float C[2][6][4];
#pragma unroll
    for (int mf = 0; mf < 2; mf++)
#pragma unroll
        for (int nf = 0; nf < 6; nf++)
#pragma unroll
            for (int q = 0; q < 4; q++) C[mf][nf][q] = 0.f;

    for (int c = 0; c < nCh; c++) {
        CP_WAIT0();
        __syncthreads();   // chunk c staged by all threads; prev chunk compute done
        if (c + 1 < nCh) {
            int st = (c + 1) & 1;
#pragma unroll
            for (int it = 0; it < 3; it++) {
                int i = tid + it * THREADS;
                int rw = i >> 2, v = i & 3;
                cp16(sW + st * W_STAGE + rw * 40 + v * 8,
                     gW + (nBase + rw) * ldW + (c + 1) * 32 + v * 8);
            }
            CP_COMMIT();
        }
        const __half* Wb = sW + (c & 1) * W_STAGE;
#pragma unroll
        for (int ks = 0; ks < 2; ks++) {
            int kb = c * 32 + ks * 16;
            const __half* Ab; int sh, ac;
            if (kb < kSplit) { Ab = A0; sh = 0; ac = kb; }
            else             { Ab = A1; sh = 4; ac = kb - kSplit; }
            uint32_t a[2][4];
#pragma unroll
            for (int mf = 0; mf < 2; mf++) {
                int row = rowBase + mf * 16 + arow;
                ldsm_x4(a[mf], Ab + (row >> sh) * strideA + ac + akof);
            }
#pragma unroll
            for (int np = 0; np < 3; np++) {
                uint32_t b4[4];
                ldsm_x4(b4, Wb + (colBase + np * 16 + brow) * 40 + ks * 16 + bkof);
#pragma unroll
                for (int half_ = 0; half_ < 2; half_++) {
                    int nf = np * 2 + half_;
                    uint32_t b0 = b4[half_ * 2], b1 = b4[half_ * 2 + 1];
#pragma unroll
                    for (int mf = 0; mf < 2; mf++) {
                        asm volatile(
                            "mma.sync.aligned.m16n8k16.row.col.f32.f16.f16.f32 "
                            "{%0,%1,%2,%3}, {%4,%5,%6,%7}, {%8,%9}, {%0,%1,%2,%3};\n"
                            : "+f"(C[mf][nf][0]), "+f"(C[mf][nf][1]),
                              "+f"(C[mf][nf][2]), "+f"(C[mf][nf][3])
                            : "r"(a[mf][0]), "r"(a[mf][1]),
                              "r"(a[mf][2]), "r"(a[mf][3]),
                              "r"(b0), "r"(b1));
                    }
                }
            }
        }
    }
    // Epilogue (no sync needed: output regions never alias this pass's A/W;
    // the next pass's first-chunk barrier orders everything).
    const int grp = lane >> 2, tig = lane & 3;
#pragma unroll
    for (int mf = 0; mf < 2; mf++) {
        int r0 = rowBase + mf * 16 + grp;
        int r1 = r0 + 8;
#pragma unroll
        for (int nf = 0; nf < 6; nf++) {
            int cl = colBase + nf * 8 + tig * 2;
            float bv0 = bias[cl];
            float bv1 = bias[cl + 1];
            float v00 = C[mf][nf][0] + bv0;
            float v01 = C[mf][nf][1] + bv1;
            float v10 = C[mf][nf][2] + bv0;
            float v11 = C[mf][nf][3] + bv1;
            if (doGelu) {                 // exact gelu: x * Phi(x)
                v00 *= normcdff(v00);
                v01 *= normcdff(v01);
                v10 *= normcdff(v10);
                v11 *= normcdff(v11);
            }
            if (outH) {
                *(__half2*)(outH + r0 * strideOutH + outColBase + cl) =
                    __floats2half2_rn(v00, v01);
                *(__half2*)(outH + r1 * strideOutH + outColBase + cl) =
                    __floats2half2_rn(v10, v11);
            } else {
                outF[r0 * strideOutF + cl]     = v00;
                outF[r0 * strideOutF + cl + 1] = v01;
                outF[r1 * strideOutF + cl]     = v10;
                outF[r1 * strideOutF + cl + 1] = v11;
            }
        }
    }
}

__global__ __launch_bounds__(THREADS, 2)
void fused_mlp_pool(const float* __restrict__ pos,
                    const int*   __restrict__ edges,
                    const float* __restrict__ b1,
                    const float* __restrict__ b2,
                    const float* __restrict__ b3,
                    float* __restrict__ out)
{
    extern __shared__ char smem[];
    __half* sSrc = (__half*)(smem);
    __half* sDst = (__half*)(smem + OFF_DST);
    __half* sH1  = (__half*)(smem + OFF_H1);
    __half* sW   = (__half*)(smem + OFF_W);
    float*  sH3  = (float*)(smem + OFF_H1);

    const int tile = blockIdx.x;                  // 64 edges per tile
    const int tid  = threadIdx.x;
    const int lane = tid & 31;
    const int wid  = tid >> 5;
    const int rowBase = (wid >> 2) * 32;          // 2 warps in M
    const int colBase = (wid & 3) * 48;           // 4 warps in N

    // ---- sincos embedding into smem (fp16), fast MUFU sin/cos ----
    // omega_j = 10000^(-j/32) = 2^(-j*log2(10000)/32); |arg| <~ 6 -> __sinf ok
    const float NLOG = -0.41524101186092033f;
    for (int i = tid; i < 64 * 96; i += THREADS) {
        int r = i / 96, q = i - r * 96;
        int d = q >> 5, j = q & 31;
        int src = edges[(tile * 64 + r) * 2 + 1];
        float cc = pos[src * 3 + d];
        float w = exp2f((float)j * NLOG);
        float x = cc * w;
        sSrc[r * 200 + d * 64 + j]      = __float2half(__sinf(x));
        sSrc[r * 200 + d * 64 + 32 + j] = __float2half(__cosf(x));
    }
    for (int i = tid; i < 4 * 96; i += THREADS) {
        int g = i / 96, q = i - g * 96;
        int d = q >> 5, j = q & 31;
        int dv = edges[(tile * 64 + g * 16) * 2];
        float cc = pos[dv * 3 + d];
        float w = exp2f((float)j * NLOG);
        float x = cc * w;
        sDst[g * 200 + d * 64 + j]      = __float2half(__sinf(x));
        sDst[g * 200 + d * 64 + 32 + j] = __float2half(__cosf(x));
    }
    // (first chunk barrier inside mma_pass makes embeddings visible)

    // Layer 1 (K=384: k<192 from sSrc rows, k>=192 from sDst[row>>4]) -> gelu
    mma_pass(tid, lane, rowBase, colBase, g_Wt1, 384, 0, 384,
             sSrc, sDst, 200, 192, sW,
             true, sH1, 392, 0, nullptr, 0, b1);
    mma_pass(tid, lane, rowBase, colBase, g_Wt1, 384, 192, 384,
             sSrc, sDst, 200, 192, sW,
             true, sH1, 392, 192, nullptr, 0, b1 + 192);
    // Layer 2: h1 @ W2 -> gelu -> h2 (reuses sSrc region)
    mma_pass(tid, lane, rowBase, colBase, g_Wt2, 384, 0, 384,
             sH1, sH1, 392, 1 << 20, sW,
             true, sSrc, 200, 0, nullptr, 0, b2);
    // Layer 3: h2 @ W3 + b3 -> fp32 sH3 (overlays sH1 region)
    mma_pass(tid, lane, rowBase, colBase, g_Wt3, 192, 0, 192,
             sSrc, sSrc, 200, 1 << 20, sW,
             false, nullptr, 0, 0, sH3, 196, b3);

    __syncthreads();
    // Segment mean: 4 groups of 16 consecutive rows, /16 (DEG exact)
    for (int i = tid; i < 4 * 192; i += THREADS) {
        int g = i / 192, c = i - g * 192;
        float s = 0.f;
#pragma unroll
        for (int r = 0; r < 16; r++) s += sH3[(g * 16 + r) * 196 + c];
        out[(tile * 4 + g) * 192 + c] = s * 0.0625f;
    }
}

extern "C" void kernel_launch(void* const* d_in, const int* in_sizes, int n_in,
                              void* d_out, int out_size) {
    const float* pos   = (const float*)d_in[0];
    const int*   edges = (const int*)d_in[1];
    // d_in[2] = batch_idx (unused by the reference computation)
    const float* W1 = (const float*)d_in[3];
    const float* b1 = (const float*)d_in[4];
    const float* W2 = (const float*)d_in[5];
    const float* b2 = (const float*)d_in[6];
    const float* W3 = (const float*)d_in[7];
    const float* b3 = (const float*)d_in[8];
    float* out = (float*)d_out;

    const int totalW = 384 * 384 + 192 * 384 + 192 * 192;
    prep_weights<<<(totalW + 255) / 256, 256>>>(W1, W2, W3);

    cudaFuncSetAttribute(fused_mlp_pool,
                         cudaFuncAttributeMaxDynamicSharedMemorySize, SMEM_TOTAL);
    fused_mlp_pool<<<4096, THREADS, SMEM_TOTAL>>>(pos, edges, b1, b2, b3, out);
}